// round 6
// baseline (speedup 1.0000x reference)
#include <cuda_runtime.h>
#include <cuda_bf16.h>

#define N_NODES 100000
#define N_EDGES 500000
#define HIDDEN 32
#define HEADS 4
#define PROJ 128   // HIDDEN*HEADS
#define LN_EPS 1e-5f

#define POS_GROUPS (N_NODES / 4)              // 25000 (N_NODES % 4 == 0)
#define POS_BLOCKS ((POS_GROUPS + 255) / 256) // 98
#define INIT_GRID (POS_BLOCKS + 3)            // 3 prep blocks lead (blockIdx 0..2)

// ---------------- scratch (static device globals; no runtime alloc) ----------
// g_seg16 starts zero (module-load zero-init); node_kernel re-zeros it after
// reading, so every kernel_launch sees zeros without a memset on the path.
__device__ float  g_seg16[N_NODES * 16];   // per-node accumulated w-vector [N,16]
__device__ float4 g_pos4[N_NODES];         // padded positions (16B aligned gather)
__device__ float  g_scoreC[HEADS * 16];    // per head: A[9], u[3], s, pad3 (all /sqrt(32))
__device__ float  g_M[HIDDEN * 16];        // M^T: [d][h*4 + {mx,my,mz,c}]
__device__ int    g_is64;                  // 1 if edge_index is int64

// ------ fused init: (blocks 0..2) prep + (rest) pack pos4, 4 nodes/thread ----
__global__ void __launch_bounds__(256) init_kernel(const float* __restrict__ pos,
                                                   const float* __restrict__ Wq,
                                                   const float* __restrict__ bq,
                                                   const float* __restrict__ Wk,
                                                   const float* __restrict__ bk,
                                                   const float* __restrict__ Wv,
                                                   const float* __restrict__ bv,
                                                   const float* __restrict__ Wout,
                                                   const int* __restrict__ ei32) {
    if (blockIdx.x >= 3) {
        int g = (blockIdx.x - 3) * blockDim.x + threadIdx.x;   // node group (4 nodes)
        if (g >= POS_GROUPS) return;
        const float4* p4 = (const float4*)pos;                  // pos is 16B aligned
        float4 a = __ldg(&p4[3 * g + 0]);   // n0.x n0.y n0.z n1.x
        float4 b = __ldg(&p4[3 * g + 1]);   // n1.y n1.z n2.x n2.y
        float4 c = __ldg(&p4[3 * g + 2]);   // n2.z n3.x n3.y n3.z
        int n = 4 * g;
        g_pos4[n + 0] = make_float4(a.x, a.y, a.z, 0.f);
        g_pos4[n + 1] = make_float4(a.w, b.x, b.y, 0.f);
        g_pos4[n + 2] = make_float4(b.z, b.w, c.x, 0.f);
        g_pos4[n + 3] = make_float4(c.y, c.z, c.w, 0.f);
        return;
    }

    // ---- prep blocks: t in [0, 768) ----
    const float invs = 0.17677669529663687f;  // 1/sqrt(32)
    int t = blockIdx.x * 256 + threadIdx.x;

    if (t < 512) {
        // M^T entries: g_M[d*16 + h*4 + j]
        int d = t >> 4;
        int idx = t & 15;
        int h = idx >> 2;
        int j = idx & 3;
        float acc = 0.f;
        if (j < 3) {
#pragma unroll 8
            for (int dd = 0; dd < 32; dd++)
                acc += Wv[j * PROJ + h * 32 + dd] * Wout[(h * 32 + dd) * HIDDEN + d];
        } else {
#pragma unroll 8
            for (int dd = 0; dd < 32; dd++)
                acc += bv[h * 32 + dd] * Wout[(h * 32 + dd) * HIDDEN + d];
        }
        g_M[t] = acc;
    } else if (t < 576) {
        int u = t - 512;
        int h = u >> 4;
        int idx = u & 15;
        float acc = 0.f;
        if (idx < 9) {
            int i = idx / 3, j = idx % 3;
#pragma unroll 8
            for (int d = 0; d < 32; d++)
                acc += Wq[i * PROJ + h * 32 + d] * Wk[j * PROJ + h * 32 + d];
        } else if (idx < 12) {
            int i = idx - 9;
#pragma unroll 8
            for (int d = 0; d < 32; d++)
                acc += Wq[i * PROJ + h * 32 + d] * bk[h * 32 + d]
                     + Wk[i * PROJ + h * 32 + d] * bq[h * 32 + d];
        } else if (idx == 12) {
#pragma unroll 8
            for (int d = 0; d < 32; d++)
                acc += bq[h * 32 + d] * bk[h * 32 + d];
        }
        g_scoreC[u] = acc * invs;
    } else if (t >= 576 && t < 608) {
        // int64 detect: one warp scans first 256 odd 32-bit words (2KB).
        int lane = t - 576;
        int acc = 0;
#pragma unroll
        for (int i = 0; i < 8; i++)
            acc |= ei32[2 * (lane * 8 + i) + 1];
        unsigned m = __ballot_sync(0xffffffffu, acc != 0);
        if (lane == 0) g_is64 = (m == 0) ? 1 : 0;
    }
}

// ------------- edge kernel: 4 edges/thread, batched loads -> softmax -> RED --
__global__ void __launch_bounds__(256) edge_kernel(const void* __restrict__ ei_raw) {
    __shared__ __align__(16) float sSc[64];
    int t = threadIdx.x;
    if (t < 64) sSc[t] = g_scoreC[t];
    __syncthreads();

    int quad = blockIdx.x * blockDim.x + t;
    if (quad >= N_EDGES / 4) return;

    int row[4], col[4];
    if (g_is64) {
        const longlong2* eiR = (const longlong2*)ei_raw;
        const longlong2* eiC = (const longlong2*)((const long long*)ei_raw + N_EDGES);
        longlong2 r0 = __ldg(&eiR[2 * quad + 0]);
        longlong2 r1 = __ldg(&eiR[2 * quad + 1]);
        longlong2 c0 = __ldg(&eiC[2 * quad + 0]);
        longlong2 c1 = __ldg(&eiC[2 * quad + 1]);
        row[0] = (int)r0.x; row[1] = (int)r0.y; row[2] = (int)r1.x; row[3] = (int)r1.y;
        col[0] = (int)c0.x; col[1] = (int)c0.y; col[2] = (int)c1.x; col[3] = (int)c1.y;
    } else {
        const int4* eiR = (const int4*)ei_raw;
        const int4* eiC = (const int4*)((const int*)ei_raw + N_EDGES);
        int4 r = __ldg(&eiR[quad]);
        int4 c = __ldg(&eiC[quad]);
        row[0] = r.x; row[1] = r.y; row[2] = r.z; row[3] = r.w;
        col[0] = c.x; col[1] = c.y; col[2] = c.z; col[3] = c.w;
    }

    // front-batch all 8 gathers (max MLP before any dependent compute)
    float4 pr[4], pc[4];
#pragma unroll
    for (int e = 0; e < 4; e++) pr[e] = g_pos4[row[e]];
#pragma unroll
    for (int e = 0; e < 4; e++) pc[e] = g_pos4[col[e]];

#pragma unroll
    for (int e = 0; e < 4; e++) {
        float x = pr[e].x - pc[e].x;
        float y = pr[e].y - pc[e].y;
        float z = pr[e].z - pc[e].z;

        // scores per head: rel^T A rel + u.rel + s (pre-scaled by 1/sqrt(32)).
        // Scores are bounded (|s| < ~20) so no max-subtraction needed in fp32.
        float sc[HEADS];
        float sum = 0.f;
#pragma unroll
        for (int h = 0; h < HEADS; h++) {
            const float* c = &sSc[16 * h];
            float t0 = c[0] * x + c[1] * y + c[2] * z;
            float t1 = c[3] * x + c[4] * y + c[5] * z;
            float t2 = c[6] * x + c[7] * y + c[8] * z;
            float s = x * t0 + y * t1 + z * t2 + c[9] * x + c[10] * y + c[11] * z + c[12];
            sc[h] = __expf(s);
            sum += sc[h];
        }
        float inv = 1.f / sum;

        float* segp = &g_seg16[(size_t)col[e] * 16];
#pragma unroll
        for (int h = 0; h < HEADS; h++) {
            float a = sc[h] * inv;
            asm volatile("red.global.add.v4.f32 [%0], {%1,%2,%3,%4};"
                         :: "l"(segp + 4 * h), "f"(a * x), "f"(a * y), "f"(a * z), "f"(a)
                         : "memory");
        }
    }
}

// ------- node kernel: fold + mean + LN + SiLU; re-zeros g_seg16 --------------
__global__ void __launch_bounds__(256) node_kernel(float* __restrict__ out,
                                                   const float* __restrict__ bout,
                                                   const float* __restrict__ gamma,
                                                   const float* __restrict__ beta) {
    __shared__ __align__(16) float sM[512];   // M^T: [d][16]
    __shared__ float sB[32], sG[32], sBe[32];
    int t = threadIdx.x;
    for (int i = t; i < 512; i += blockDim.x) sM[i] = g_M[i];
    if (t < 32) { sB[t] = __ldg(&bout[t]); sG[t] = __ldg(&gamma[t]); sBe[t] = __ldg(&beta[t]); }
    __syncthreads();

    int node = blockIdx.x * blockDim.x + t;
    if (node >= N_NODES) return;

    float4* Wp = (float4*)&g_seg16[(size_t)node * 16];
    float4 w0 = Wp[0], w1 = Wp[1], w2 = Wp[2], w3 = Wp[3];
    // restore the zero-state invariant for the next launch/replay
    float4 z = make_float4(0.f, 0.f, 0.f, 0.f);
    Wp[0] = z; Wp[1] = z; Wp[2] = z; Wp[3] = z;

    float cnt = w0.w + w1.w + w2.w + w3.w;          // exact edge count (sum of attn = 1)
    float invc = 1.f / fmaxf(cnt, 1.f);

    const float4* sM4 = (const float4*)sM;
    float o[32];
    float mean = 0.f;
#pragma unroll
    for (int d = 0; d < 32; d++) {
        float4 m0 = sM4[d * 4 + 0];
        float4 m1 = sM4[d * 4 + 1];
        float4 m2 = sM4[d * 4 + 2];
        float4 m3 = sM4[d * 4 + 3];
        float acc = w0.x * m0.x + w0.y * m0.y + w0.z * m0.z + w0.w * m0.w
                  + w1.x * m1.x + w1.y * m1.y + w1.z * m1.z + w1.w * m1.w
                  + w2.x * m2.x + w2.y * m2.y + w2.z * m2.z + w2.w * m2.w
                  + w3.x * m3.x + w3.y * m3.y + w3.z * m3.z + w3.w * m3.w;
        o[d] = acc * invc + sB[d];
        mean += o[d];
    }
    mean *= (1.f / 32.f);
    float var = 0.f;
#pragma unroll
    for (int d = 0; d < 32; d++) {
        float dd = o[d] - mean;
        var += dd * dd;
    }
    float rstd = rsqrtf(var * (1.f / 32.f) + LN_EPS);

    float4* outp = (float4*)&out[(size_t)node * 32];
#pragma unroll
    for (int d4 = 0; d4 < 8; d4++) {
        float4 r;
        float y0 = (o[d4*4+0] - mean) * rstd * sG[d4*4+0] + sBe[d4*4+0];
        float y1 = (o[d4*4+1] - mean) * rstd * sG[d4*4+1] + sBe[d4*4+1];
        float y2 = (o[d4*4+2] - mean) * rstd * sG[d4*4+2] + sBe[d4*4+2];
        float y3 = (o[d4*4+3] - mean) * rstd * sG[d4*4+3] + sBe[d4*4+3];
        r.x = y0 / (1.f + __expf(-y0));
        r.y = y1 / (1.f + __expf(-y1));
        r.z = y2 / (1.f + __expf(-y2));
        r.w = y3 / (1.f + __expf(-y3));
        outp[d4] = r;
    }
}

// ---------------- launch ------------------------------------------------------
extern "C" void kernel_launch(void* const* d_in, const int* in_sizes, int n_in,
                              void* d_out, int out_size) {
    const float* pos  = (const float*)d_in[0];
    const void*  ei   = d_in[1];
    const float* Wq   = (const float*)d_in[2];
    const float* bq   = (const float*)d_in[3];
    const float* Wk   = (const float*)d_in[4];
    const float* bk   = (const float*)d_in[5];
    const float* Wv   = (const float*)d_in[6];
    const float* bv   = (const float*)d_in[7];
    const float* Wout = (const float*)d_in[8];
    const float* bout = (const float*)d_in[9];
    const float* gamma= (const float*)d_in[10];
    const float* beta = (const float*)d_in[11];

    init_kernel<<<INIT_GRID, 256>>>(pos, Wq, bq, Wk, bk, Wv, bv, Wout, (const int*)ei);
    edge_kernel<<<(N_EDGES / 4 + 255) / 256, 256>>>(ei);
    node_kernel<<<(N_NODES + 255) / 256, 256>>>((float*)d_out, bout, gamma, beta);
}